// round 14
// baseline (speedup 1.0000x reference)
#include <cuda_runtime.h>
#include <cuda_bf16.h>
#include <cstdint>

#define BB      32
#define HH      8
#define WW2     32
#define PP      256
#define CF      512
#define AA      512
#define RR      512
#define VV1     111
#define NSTEPS  31
#define NBLK    128
#define NTHR    512

#define PY      10
#define PX      34

// ---------------- device scratch ----------------
__device__ float g_fp[(size_t)BB * PP * AA];
__device__ float g_h0[2][BB * RR];
__device__ float g_h1h[32][BB * RR];    // h1 history: slot t+1 = h1(t); slot 0 = zeros
__device__ float g_c0[BB * RR];
__device__ float g_c1[BB * RR];
__device__ float g_xg[(size_t)2048 * 1024];   // precomputed wih0 @ x : [row][t*32+b]
__device__ unsigned g_arr[NBLK];              // store-based arrival epochs
__device__ unsigned g_rel[NBLK];

__device__ __nv_bfloat16 g_fa_hi[(size_t)BB * PY * PX * CF];
__device__ __nv_bfloat16 g_fa_lo[(size_t)BB * PY * PX * CF];
__device__ __nv_bfloat16 g_wb_hi[(size_t)9 * AA * CF];
__device__ __nv_bfloat16 g_wb_lo[(size_t)9 * AA * CF];
__device__ __nv_bfloat16 g_wA_hi[(size_t)2048 * 512];
__device__ __nv_bfloat16 g_wA_lo[(size_t)2048 * 512];
__device__ __nv_bfloat16 g_xb_hi[(size_t)1024 * 512];
__device__ __nv_bfloat16 g_xb_lo[(size_t)1024 * 512];

__device__ __forceinline__ float tanh_fast(float x) {
    float y;
    asm("tanh.approx.f32 %0, %1;" : "=f"(y) : "f"(x));
    return y;
}

// store-based barrier: each block stores its epoch to a private slot (no atomic
// serialization); block 0 polls all slots in parallel, fans out releases.
__device__ __forceinline__ void grid_bar(int blk, unsigned ep) {
    __syncthreads();
    if (blk == 0) {
        if (threadIdx.x == 0) __threadfence();
        if (threadIdx.x > 0 && threadIdx.x < NBLK) {
            while (*(volatile unsigned*)&g_arr[threadIdx.x] < ep) { }
        }
        __syncthreads();
        if (threadIdx.x == 0) __threadfence();
        __syncthreads();
        if (threadIdx.x > 0 && threadIdx.x < NBLK)
            *(volatile unsigned*)&g_rel[threadIdx.x] = ep;
    } else {
        if (threadIdx.x == 0) {
            __threadfence();
            *(volatile unsigned*)&g_arr[blk] = ep;
            while (*(volatile unsigned*)&g_rel[blk] < ep) { }
            __threadfence();
        }
    }
    __syncthreads();
}

__device__ __forceinline__ uint32_t smem_u32(const void* p) {
    uint32_t a;
    asm("{ .reg .u64 t; cvta.to.shared.u64 t, %1; cvt.u32.u64 %0, t; }" : "=r"(a) : "l"(p));
    return a;
}

#define SW128(o) ((o) ^ (((o) >> 3) & 0x70))

__device__ __forceinline__ void cp16(uint32_t s, const void* g) {
    asm volatile("cp.async.cg.shared.global [%0], [%1], 16;" :: "r"(s), "l"(g) : "memory");
}

#define LDSM4(r, addr) \
    asm volatile("ldmatrix.sync.aligned.m8n8.x4.shared.b16 {%0,%1,%2,%3}, [%4];" \
        : "=r"((r)[0]), "=r"((r)[1]), "=r"((r)[2]), "=r"((r)[3]) : "r"(addr))

#define MMA16816(d, a, b) \
    asm volatile("mma.sync.aligned.m16n8k16.row.col.f32.bf16.bf16.f32 " \
        "{%0,%1,%2,%3}, {%4,%5,%6,%7}, {%8,%9}, {%0,%1,%2,%3};" \
        : "+f"((d)[0]), "+f"((d)[1]), "+f"((d)[2]), "+f"((d)[3]) \
        : "r"((a)[0]), "r"((a)[1]), "r"((a)[2]), "r"((a)[3]), "r"((b)[0]), "r"((b)[1]))

#define FMA2(acc, w, aa) \
    asm("fma.rn.f32x2 %0, %1, %2, %0;" : "+l"(acc) : "l"(w), "l"(aa))

#define PACK2(aa, f) \
    do { uint32_t _u = __float_as_uint(f); \
         asm("mov.b64 %0, {%1, %1};" : "=l"(aa) : "r"(_u)); } while (0)

__device__ __forceinline__ unsigned long long wredsum2(unsigned long long v) {
#pragma unroll
    for (int o = 16; o; o >>= 1) {
        unsigned long long u = __shfl_xor_sync(0xffffffffu, v, o);
        asm("add.rn.f32x2 %0, %0, %1;" : "+l"(v) : "l"(u));
    }
    return v;
}

__device__ __forceinline__ float u64lo(unsigned long long v) { return __uint_as_float((uint32_t)v); }
__device__ __forceinline__ float u64hi(unsigned long long v) { return __uint_as_float((uint32_t)(v >> 32)); }

// ---------------- merged init: states + barrier words + x bf16 + wih0 bf16 + zero pads --
__global__ void k_init(const int* __restrict__ gt, const float* __restrict__ W_embed,
                       const float* __restrict__ wih0) {
    int idx = blockIdx.x * 256 + threadIdx.x;        // 4096 x 256 = 1048576
    if (idx < NBLK) { g_arr[idx] = 0; g_rel[idx] = 0; }
    if (idx < BB * RR) {
        g_h0[0][idx] = 0.f;
        g_h0[1][idx] = 0.f;
        g_h1h[0][idx] = 0.f;
        g_c0[idx] = 0.f;
        g_c1[idx] = 0.f;
    }
    if (idx < 1024 * 512) {
        int n = idx >> 9, r = idx & 511;
        int t = n >> 5, b = n & 31;
        float v = 0.f;
        if (t >= 1 && t <= 30) {
            int g = gt[b * NSTEPS + t - 1];
            v = W_embed[r * VV1 + g];
        }
        __nv_bfloat16 hi = __float2bfloat16(v);
        __nv_bfloat16 lo = __float2bfloat16(v - __bfloat162float(hi));
        g_xb_hi[idx] = hi;
        g_xb_lo[idx] = lo;
    }
    {   // wih0 -> bf16 hi/lo (exactly 1M elements = grid size)
        float v = wih0[idx];
        __nv_bfloat16 hi = __float2bfloat16(v);
        __nv_bfloat16 lo = __float2bfloat16(v - __bfloat162float(hi));
        g_wA_hi[idx] = hi;
        g_wA_lo[idx] = lo;
    }
    {   // zero padded feature arrays (u32 grid-stride)
        size_t n = (size_t)BB * PY * PX * CF / 2;
        uint32_t* a = (uint32_t*)g_fa_hi;
        uint32_t* b = (uint32_t*)g_fa_lo;
        for (size_t i = idx; i < n; i += (size_t)4096 * 256) {
            a[i] = 0u;
            b[i] = 0u;
        }
    }
}

// ---------------- conv prep kernels ----------------
__global__ void k_prep_feat(const float* __restrict__ feat) {
    __shared__ float sm[32][33];
    int pblk = blockIdx.x, c0 = blockIdx.y * 32, b = blockIdx.z;
    int tx = threadIdx.x, ty = threadIdx.y;
    sm[ty][tx] = feat[((size_t)b * CF + c0 + ty) * PP + pblk * 32 + tx];
    __syncthreads();
    int c = c0 + tx;
    float v = sm[tx][ty];
    __nv_bfloat16 hi = __float2bfloat16(v);
    __nv_bfloat16 lo = __float2bfloat16(v - __bfloat162float(hi));
    size_t o = (((size_t)b * PY + (pblk + 1)) * PX + (ty + 1)) * CF + c;
    g_fa_hi[o] = hi;
    g_fa_lo[o] = lo;
}

__global__ void k_prep_w(const float* __restrict__ Wf) {
    __shared__ float wrow[CF * 9];
    int a = blockIdx.x, tid = threadIdx.x;
    for (int i = tid; i < CF * 9; i += 256) wrow[i] = Wf[(size_t)a * CF * 9 + i];
    __syncthreads();
    for (int tap = 0; tap < 9; tap++) {
        for (int c = tid; c < CF; c += 256) {
            float v = wrow[c * 9 + tap];
            __nv_bfloat16 hi = __float2bfloat16(v);
            __nv_bfloat16 lo = __float2bfloat16(v - __bfloat162float(hi));
            size_t o = ((size_t)tap * AA + a) * CF + c;
            g_wb_hi[o] = hi;
            g_wb_lo[o] = lo;
        }
    }
}

// ---------------- tensor-core conv (R7/R11 proven version: 256 CTAs) ----------------
#define CSTAGE 65536
#define CONV_SMEM (2 * CSTAGE + 1024)

__global__ void __launch_bounds__(256) k_conv_mma(const float* __restrict__ bfeat) {
    extern __shared__ char dsm[];
    uint32_t sb = (smem_u32(dsm) + 1023) & ~1023u;

    int tid = threadIdx.x;
    int lane = tid & 31, wid = tid >> 5;
    int warp_m = wid & 1, warp_n = wid >> 1;

    int Ntile = blockIdx.x & 3;
    int Mtile = blockIdx.x >> 2;
    int n0 = Ntile * 128;
    int b = Mtile >> 1;
    int p0 = (Mtile & 1) * 128;

    int arow = tid >> 1, ahalf = tid & 1;
    int p = p0 + arow;
    int ay = p >> 5, ax = p & 31;

    int kh_a = lane >> 4;
    int row_l = lane & 15;
    uint32_t aoff[4], axorm[4];
#pragma unroll
    for (int mi = 0; mi < 4; mi++) {
        int row = warp_m * 64 + mi * 16 + row_l;
        aoff[mi] = row * 128;
        axorm[mi] = (row & 7) << 4;
    }
    int kh_b = (lane >> 3) & 1;
    int n_l = (lane & 7) + ((lane >> 4) << 3);
    uint32_t boff[2], bxorm[2];
#pragma unroll
    for (int np = 0; np < 2; np++) {
        int n = warp_n * 32 + np * 16 + n_l;
        boff[np] = n * 128;
        bxorm[np] = (n & 7) << 4;
    }

    float acc[4][4][4];
#pragma unroll
    for (int mi = 0; mi < 4; mi++)
#pragma unroll
        for (int ni = 0; ni < 4; ni++)
#pragma unroll
            for (int q = 0; q < 4; q++) acc[mi][ni][q] = 0.f;

    auto issue_chunk = [&](int chunk, int st) {
        int tap = chunk >> 3, cblk = chunk & 7;
        int ky = tap / 3, kx = tap - ky * 3;
        uint32_t sbase = sb + st * CSTAGE;
        size_t ga = (((size_t)b * PY + (ay + ky)) * PX + (ax + kx)) * CF
                  + cblk * 64 + ahalf * 32;
        size_t gb = ((size_t)tap * AA + n0 + arow) * CF + cblk * 64 + ahalf * 32;
        const char* pahi = (const char*)(g_fa_hi + ga);
        const char* palo = (const char*)(g_fa_lo + ga);
        const char* pbhi = (const char*)(g_wb_hi + gb);
        const char* pblo = (const char*)(g_wb_lo + gb);
#pragma unroll
        for (int q = 0; q < 4; q++) {
            uint32_t off = arow * 128 + ahalf * 64 + q * 16;
            uint32_t sw = SW128(off);
            cp16(sbase + sw,          pahi + q * 16);
            cp16(sbase + 16384 + sw,  palo + q * 16);
            cp16(sbase + 32768 + sw,  pbhi + q * 16);
            cp16(sbase + 49152 + sw,  pblo + q * 16);
        }
        asm volatile("cp.async.commit_group;" ::: "memory");
    };

    issue_chunk(0, 0);

#pragma unroll 1
    for (int it = 0; it < 72; it++) {
        int st = it & 1;
        asm volatile("cp.async.wait_group 0;" ::: "memory");
        __syncthreads();
        if (it + 1 < 72) issue_chunk(it + 1, st ^ 1);

        uint32_t Ab = sb + st * CSTAGE;
        uint32_t Bb = Ab + 32768;
#pragma unroll
        for (int ks = 0; ks < 4; ks++) {
            uint32_t ahi[4][4], alo[4][4], bhi[4][2], blo[4][2];
            uint32_t kca = ks * 32 + kh_a * 16;
            uint32_t kcb = ks * 32 + kh_b * 16;
#pragma unroll
            for (int mi = 0; mi < 4; mi++) {
                uint32_t ad = Ab + aoff[mi] + (kca ^ axorm[mi]);
                LDSM4(ahi[mi], ad);
                LDSM4(alo[mi], ad + 16384);
            }
#pragma unroll
            for (int np = 0; np < 2; np++) {
                uint32_t bd = Bb + boff[np] + (kcb ^ bxorm[np]);
                uint32_t r[4];
                LDSM4(r, bd);
                bhi[np * 2][0] = r[0]; bhi[np * 2][1] = r[1];
                bhi[np * 2 + 1][0] = r[2]; bhi[np * 2 + 1][1] = r[3];
                LDSM4(r, bd + 16384);
                blo[np * 2][0] = r[0]; blo[np * 2][1] = r[1];
                blo[np * 2 + 1][0] = r[2]; blo[np * 2 + 1][1] = r[3];
            }
#pragma unroll
            for (int mi = 0; mi < 4; mi++)
#pragma unroll
                for (int ni = 0; ni < 4; ni++) {
                    MMA16816(acc[mi][ni], ahi[mi], bhi[ni]);
                    MMA16816(acc[mi][ni], ahi[mi], blo[ni]);
                    MMA16816(acc[mi][ni], alo[mi], bhi[ni]);
                }
        }
    }

    int rgrp = lane >> 2, cpair = (lane & 3) * 2;
    float bs0[4], bs1[4];
#pragma unroll
    for (int ni = 0; ni < 4; ni++) {
        int a = n0 + warp_n * 32 + ni * 8 + cpair;
        bs0[ni] = bfeat[a];
        bs1[ni] = bfeat[a + 1];
    }
#pragma unroll
    for (int mi = 0; mi < 4; mi++) {
#pragma unroll
        for (int h = 0; h < 2; h++) {
            int m = Mtile * 128 + warp_m * 64 + mi * 16 + rgrp + h * 8;
            int obb = m >> 8, op = m & 255;
            float* dst = g_fp + ((size_t)obb * PP + op) * AA + n0 + warp_n * 32;
#pragma unroll
            for (int ni = 0; ni < 4; ni++) {
                float2 v;
                v.x = acc[mi][ni][h * 2 + 0] + bs0[ni];
                v.y = acc[mi][ni][h * 2 + 1] + bs1[ni];
                *(float2*)(dst + ni * 8 + cpair) = v;
            }
        }
    }
}

// ---------------- xg GEMM: xg[2048 x 1024] = wih0 @ x^T (bf16 3-term) ----------------
__global__ void __launch_bounds__(256) k_xgemm() {
    extern __shared__ char dsm[];
    uint32_t sb = (smem_u32(dsm) + 1023) & ~1023u;

    int tid = threadIdx.x;
    int lane = tid & 31, wid = tid >> 5;
    int warp_m = wid & 1, warp_n = wid >> 1;

    int Mtile = blockIdx.x >> 3;
    int Ntile = blockIdx.x & 7;
    int m0 = Mtile * 128, n0 = Ntile * 128;

    int arow = tid >> 1, ahalf = tid & 1;

    int kh_a = lane >> 4;
    int row_l = lane & 15;
    uint32_t aoff[4], axorm[4];
#pragma unroll
    for (int mi = 0; mi < 4; mi++) {
        int row = warp_m * 64 + mi * 16 + row_l;
        aoff[mi] = row * 128;
        axorm[mi] = (row & 7) << 4;
    }
    int kh_b = (lane >> 3) & 1;
    int n_l = (lane & 7) + ((lane >> 4) << 3);
    uint32_t boff[2], bxorm[2];
#pragma unroll
    for (int np = 0; np < 2; np++) {
        int n = warp_n * 32 + np * 16 + n_l;
        boff[np] = n * 128;
        bxorm[np] = (n & 7) << 4;
    }

    float acc[4][4][4];
#pragma unroll
    for (int mi = 0; mi < 4; mi++)
#pragma unroll
        for (int ni = 0; ni < 4; ni++)
#pragma unroll
            for (int q = 0; q < 4; q++) acc[mi][ni][q] = 0.f;

    auto issue_chunk = [&](int cblk, int st) {
        uint32_t sbase = sb + st * CSTAGE;
        size_t ga = (size_t)(m0 + arow) * 512 + cblk * 64 + ahalf * 32;
        size_t gb = (size_t)(n0 + arow) * 512 + cblk * 64 + ahalf * 32;
        const char* pahi = (const char*)(g_wA_hi + ga);
        const char* palo = (const char*)(g_wA_lo + ga);
        const char* pbhi = (const char*)(g_xb_hi + gb);
        const char* pblo = (const char*)(g_xb_lo + gb);
#pragma unroll
        for (int q = 0; q < 4; q++) {
            uint32_t off = arow * 128 + ahalf * 64 + q * 16;
            uint32_t sw = SW128(off);
            cp16(sbase + sw,          pahi + q * 16);
            cp16(sbase + 16384 + sw,  palo + q * 16);
            cp16(sbase + 32768 + sw,  pbhi + q * 16);
            cp16(sbase + 49152 + sw,  pblo + q * 16);
        }
        asm volatile("cp.async.commit_group;" ::: "memory");
    };

    issue_chunk(0, 0);

#pragma unroll 1
    for (int it = 0; it < 8; it++) {
        int st = it & 1;
        asm volatile("cp.async.wait_group 0;" ::: "memory");
        __syncthreads();
        if (it + 1 < 8) issue_chunk(it + 1, st ^ 1);

        uint32_t Ab = sb + st * CSTAGE;
        uint32_t Bb = Ab + 32768;
#pragma unroll
        for (int ks = 0; ks < 4; ks++) {
            uint32_t ahi[4][4], alo[4][4], bhi[4][2], blo[4][2];
            uint32_t kca = ks * 32 + kh_a * 16;
            uint32_t kcb = ks * 32 + kh_b * 16;
#pragma unroll
            for (int mi = 0; mi < 4; mi++) {
                uint32_t ad = Ab + aoff[mi] + (kca ^ axorm[mi]);
                LDSM4(ahi[mi], ad);
                LDSM4(alo[mi], ad + 16384);
            }
#pragma unroll
            for (int np = 0; np < 2; np++) {
                uint32_t bd = Bb + boff[np] + (kcb ^ bxorm[np]);
                uint32_t r[4];
                LDSM4(r, bd);
                bhi[np * 2][0] = r[0]; bhi[np * 2][1] = r[1];
                bhi[np * 2 + 1][0] = r[2]; bhi[np * 2 + 1][1] = r[3];
                LDSM4(r, bd + 16384);
                blo[np * 2][0] = r[0]; blo[np * 2][1] = r[1];
                blo[np * 2 + 1][0] = r[2]; blo[np * 2 + 1][1] = r[3];
            }
#pragma unroll
            for (int mi = 0; mi < 4; mi++)
#pragma unroll
                for (int ni = 0; ni < 4; ni++) {
                    MMA16816(acc[mi][ni], ahi[mi], bhi[ni]);
                    MMA16816(acc[mi][ni], ahi[mi], blo[ni]);
                    MMA16816(acc[mi][ni], alo[mi], bhi[ni]);
                }
        }
    }

    int rgrp = lane >> 2, cpair = (lane & 3) * 2;
#pragma unroll
    for (int mi = 0; mi < 4; mi++) {
#pragma unroll
        for (int h = 0; h < 2; h++) {
            int m = m0 + warp_m * 64 + mi * 16 + rgrp + h * 8;
            float* dst = g_xg + (size_t)m * 1024 + n0 + warp_n * 32;
#pragma unroll
            for (int ni = 0; ni < 4; ni++) {
                float2 v;
                v.x = acc[mi][ni][h * 2 + 0];
                v.y = acc[mi][ni][h * 2 + 1];
                *(float2*)(dst + ni * 8 + cpair) = v;
            }
        }
    }
}

// ---------------- persistent LSTM: 512 thr, 4-way k-split, merged dual epilogue ---------
__global__ void __launch_bounds__(NTHR) k_lstm(
    const float* __restrict__ whh0,
    const float* __restrict__ bih0, const float* __restrict__ bhh0,
    const float* __restrict__ wih1, const float* __restrict__ whh1,
    const float* __restrict__ bih1, const float* __restrict__ bhh1)
{
    extern __shared__ float smdyn[];
    float* Wsm   = smdyn;             // 24576 : 3 regions x 8 pair-rows x 1024
    float* acts  = Wsm + 24576;       // 16512 : 32 b x 516
    float* gredA = acts + 16512;      // 2112  : cell1 partials [4 ksp][16 lr][33]
    float* gredB = gredA + 2112;      // 2112  : cell0 partials
    float* bsum  = gredB + 2112;      // 32

    int tid = threadIdx.x, blk = blockIdx.x;
    int j0 = blk * 4;
    int lane = tid & 31;
    int rg = (tid >> 5) & 3;
    int ksp = tid >> 7;              // 0..3

    // prologue: weights for regions {wih1, whh0, whh1}
    {
        const float* srcs[3] = {wih1, whh0, whh1};
        int pr = (tid >> 5) & 7;
        int half = tid >> 8;
        int lr0 = 2 * pr, lr1 = 2 * pr + 1;
        int r0 = (lr0 & 3) * 512 + j0 + (lr0 >> 2);
        int r1 = (lr1 & 3) * 512 + j0 + (lr1 >> 2);
#pragma unroll 1
        for (int rr2 = 0; rr2 < 3; rr2++) {
            const float* W = srcs[rr2];
            float* dst = Wsm + rr2 * 8192 + pr * 1024;
#pragma unroll
            for (int q = 0; q < 8; q++) {
                int k = (half * 8 + q) * 32 + lane;
                dst[2 * k]     = W[(size_t)r0 * 512 + k];
                dst[2 * k + 1] = W[(size_t)r1 * 512 + k];
            }
        }
    }
    if (tid < 32) {
        int cell = tid >> 4, lr = tid & 15;
        int row = (lr & 3) * 512 + j0 + (lr >> 2);
        bsum[tid] = (cell ? (bih1[row] + bhh1[row]) : (bih0[row] + bhh0[row]));
    }
    __syncthreads();

    uint32_t acts_b = smem_u32(acts);
    int sb = tid >> 4, smi = tid & 15;

    auto stage = [&](const float* src) {
        __syncthreads();
        uint32_t dstb = acts_b + sb * 516 * 4 + smi * 16;
        const float* gsrc = src + sb * 512 + smi * 4;
#pragma unroll
        for (int q = 0; q < 8; q++) cp16(dstb + q * 256, gsrc + q * 64);
        asm volatile("cp.async.commit_group;" ::: "memory");
        asm volatile("cp.async.wait_group 0;" ::: "memory");
        __syncthreads();
    };

    auto accum = [&](int regionBase, uint64_t& a0, uint64_t& a1) {
        const float* wp0 = Wsm + regionBase + (rg * 2) * 1024 + ksp * 256;
        const float* wp1 = wp0 + 1024;
        const float* ab = acts + lane * 516 + ksp * 128;
#pragma unroll 8
        for (int kk = 0; kk < 128; kk += 4) {
            float4 a4 = *(const float4*)&ab[kk];
            ulonglong2 wA = *(const ulonglong2*)&wp0[kk * 2];
            ulonglong2 wB = *(const ulonglong2*)&wp0[kk * 2 + 4];
            ulonglong2 wC = *(const ulonglong2*)&wp1[kk * 2];
            ulonglong2 wD = *(const ulonglong2*)&wp1[kk * 2 + 4];
            uint64_t aa;
            PACK2(aa, a4.x);
            FMA2(a0, wA.x, aa); FMA2(a1, wC.x, aa);
            PACK2(aa, a4.y);
            FMA2(a0, wA.y, aa); FMA2(a1, wC.y, aa);
            PACK2(aa, a4.z);
            FMA2(a0, wB.x, aa); FMA2(a1, wD.x, aa);
            PACK2(aa, a4.w);
            FMA2(a0, wB.y, aa); FMA2(a1, wD.y, aa);
        }
    };

    auto put_gred = [&](float* gr0, uint64_t a0, uint64_t a1) {
        float* gr = gr0 + ksp * 528 + (rg * 4) * 33 + lane;
        gr[0]  = u64lo(a0);
        gr[33] = u64hi(a0);
        gr[66] = u64lo(a1);
        gr[99] = u64hi(a1);
    };

    // ---- step 0 cell0: pure xg + bias ----
    if (tid < 128) {
        int u = tid >> 5, b2 = tid & 31;
        float ai = g_xg[(size_t)(0 * 512 + j0 + u) * 1024 + b2] + bsum[u * 4 + 0];
        float ag = g_xg[(size_t)(2 * 512 + j0 + u) * 1024 + b2] + bsum[u * 4 + 2];
        float ao = g_xg[(size_t)(3 * 512 + j0 + u) * 1024 + b2] + bsum[u * 4 + 3];
        float si2 = 1.f / (1.f + __expf(-ai));
        float so  = 1.f / (1.f + __expf(-ao));
        float tg  = tanhf(ag);
        int o = b2 * 512 + j0 + u;
        float cn = si2 * tg;
        g_c0[o] = cn;
        g_h0[0][o] = so * tanhf(cn);
    }
    grid_bar(blk, 1);
    unsigned ep = 1;

#pragma unroll 1
    for (int t = 0; t < NSTEPS; t++) {
        int p = t & 1;
        bool lastt = (t == NSTEPS - 1);

        // prefetch next cell0 x-gates into threads 128..255 (who run cell0 epilogue)
        float xr0 = 0.f, xr1 = 0.f, xr2 = 0.f, xr3 = 0.f;
        if (tid >= 128 && tid < 256 && !lastt) {
            int u = (tid - 128) >> 5, b2 = tid & 31;
            size_t cb = (size_t)(t + 1) * 32 + b2;
            xr0 = __ldg(&g_xg[(size_t)(0 * 512 + j0 + u) * 1024 + cb]);
            xr1 = __ldg(&g_xg[(size_t)(1 * 512 + j0 + u) * 1024 + cb]);
            xr2 = __ldg(&g_xg[(size_t)(2 * 512 + j0 + u) * 1024 + cb]);
            xr3 = __ldg(&g_xg[(size_t)(3 * 512 + j0 + u) * 1024 + cb]);
        }

        uint64_t c1a0 = 0ull, c1a1 = 0ull;
        uint64_t c0a0 = 0ull, c0a1 = 0ull;

        stage(g_h0[p]);                      // h0(t)
        accum(0, c1a0, c1a1);                // wih1 @ h0(t)
        if (!lastt) accum(8192, c0a0, c0a1); // whh0 @ h0(t)

        stage(g_h1h[t]);                     // h1(t-1)
        accum(16384, c1a0, c1a1);            // whh1 @ h1(t-1)

        // merged dual epilogue: single sync, cell1 on warps 0-3, cell0 on warps 4-7
        put_gred(gredA, c1a0, c1a1);
        if (!lastt) put_gred(gredB, c0a0, c0a1);
        __syncthreads();
        if (tid < 128) {
            int u = tid >> 5, b2 = tid & 31;
            int lrb = u * 4;
            float ai = gredA[(lrb + 0) * 33 + b2] + gredA[528 + (lrb + 0) * 33 + b2]
                     + gredA[1056 + (lrb + 0) * 33 + b2] + gredA[1584 + (lrb + 0) * 33 + b2] + bsum[16 + lrb + 0];
            float af = gredA[(lrb + 1) * 33 + b2] + gredA[528 + (lrb + 1) * 33 + b2]
                     + gredA[1056 + (lrb + 1) * 33 + b2] + gredA[1584 + (lrb + 1) * 33 + b2] + bsum[16 + lrb + 1];
            float ag = gredA[(lrb + 2) * 33 + b2] + gredA[528 + (lrb + 2) * 33 + b2]
                     + gredA[1056 + (lrb + 2) * 33 + b2] + gredA[1584 + (lrb + 2) * 33 + b2] + bsum[16 + lrb + 2];
            float ao = gredA[(lrb + 3) * 33 + b2] + gredA[528 + (lrb + 3) * 33 + b2]
                     + gredA[1056 + (lrb + 3) * 33 + b2] + gredA[1584 + (lrb + 3) * 33 + b2] + bsum[16 + lrb + 3];
            float si2 = 1.f / (1.f + __expf(-ai));
            float sf  = 1.f / (1.f + __expf(-af));
            float so  = 1.f / (1.f + __expf(-ao));
            float tg  = tanhf(ag);
            int o = b2 * 512 + j0 + u;
            float cn = sf * g_c1[o] + si2 * tg;
            g_c1[o] = cn;
            g_h1h[t + 1][o] = so * tanhf(cn);
        } else if (tid < 256 && !lastt) {
            int u = (tid - 128) >> 5, b2 = tid & 31;
            int lrb = u * 4;
            float ai = gredB[(lrb + 0) * 33 + b2] + gredB[528 + (lrb + 0) * 33 + b2]
                     + gredB[1056 + (lrb + 0) * 33 + b2] + gredB[1584 + (lrb + 0) * 33 + b2] + xr0 + bsum[lrb + 0];
            float af = gredB[(lrb + 1) * 33 + b2] + gredB[528 + (lrb + 1) * 33 + b2]
                     + gredB[1056 + (lrb + 1) * 33 + b2] + gredB[1584 + (lrb + 1) * 33 + b2] + xr1 + bsum[lrb + 1];
            float ag = gredB[(lrb + 2) * 33 + b2] + gredB[528 + (lrb + 2) * 33 + b2]
                     + gredB[1056 + (lrb + 2) * 33 + b2] + gredB[1584 + (lrb + 2) * 33 + b2] + xr2 + bsum[lrb + 2];
            float ao = gredB[(lrb + 3) * 33 + b2] + gredB[528 + (lrb + 3) * 33 + b2]
                     + gredB[1056 + (lrb + 3) * 33 + b2] + gredB[1584 + (lrb + 3) * 33 + b2] + xr3 + bsum[lrb + 3];
            float si2 = 1.f / (1.f + __expf(-ai));
            float sf  = 1.f / (1.f + __expf(-af));
            float so  = 1.f / (1.f + __expf(-ao));
            float tg  = tanhf(ag);
            int o = b2 * 512 + j0 + u;
            float cn = sf * g_c0[o] + si2 * tg;
            g_c0[o] = cn;
            g_h0[p ^ 1][o] = so * tanhf(cn);
        }
        grid_bar(blk, ++ep);
    }
}

// ---------------- attention + output (unchanged) ----------------
#define ATT_SMEM 59680

__global__ void __launch_bounds__(256) k_attn(
    const float* __restrict__ feat,
    const float* __restrict__ Wst, const float* __restrict__ watt,
    const float* __restrict__ Wout, const float* __restrict__ bout,
    float* __restrict__ out)
{
    extern __shared__ float asmem[];
    float2* h1p  = (float2*)asmem;
    float2* spp  = h1p + 2048;
    float2* attp = spp + 2048;
    float2* glp  = attp + 1024;
    float*  was_s = (float*)(glp + 2048);
    float2* red8p = (float2*)(was_s + 512);
    float2* sinvp = red8p + 32;

    int b = blockIdx.x, tg = blockIdx.y;
    int t0 = tg * 8;
    int nt = (t0 + 8 <= NSTEPS) ? 8 : (NSTEPS - t0);
    int tid = threadIdx.x, lane = tid & 31, w = tid >> 5;

    for (int i = tid; i < 512; i += 256) {
        was_s[i] = watt[i];
#pragma unroll
        for (int tp = 0; tp < 4; tp++) {
            int ja = 2 * tp, jb = 2 * tp + 1;
            float v0 = (ja < nt) ? g_h1h[t0 + ja + 1][b * 512 + i] : 0.f;
            float v1 = (jb < nt) ? g_h1h[t0 + jb + 1][b * 512 + i] : 0.f;
            h1p[tp * 512 + i] = make_float2(v0, v1);
        }
    }
    __syncthreads();

#pragma unroll 1
    for (int a = w; a < 512; a += 8) {
        uint64_t acc[4] = {0ull, 0ull, 0ull, 0ull};
        const float2* wr = (const float2*)(Wst + (size_t)a * 512);
#pragma unroll
        for (int i = 0; i < 8; i++) {
            int k2 = lane + 32 * i;
            float2 wv = wr[k2];
            uint64_t wp;
#pragma unroll
            for (int tp = 0; tp < 4; tp++) {
                ulonglong2 hq = *(const ulonglong2*)&h1p[tp * 512 + 2 * k2];
                PACK2(wp, wv.x); FMA2(acc[tp], hq.x, wp);
                PACK2(wp, wv.y); FMA2(acc[tp], hq.y, wp);
            }
        }
#pragma unroll
        for (int tp = 0; tp < 4; tp++) acc[tp] = wredsum2(acc[tp]);
        if (lane == 0) {
#pragma unroll
            for (int tp = 0; tp < 4; tp++)
                spp[tp * 512 + a] = make_float2(u64lo(acc[tp]), u64hi(acc[tp]));
        }
    }
    __syncthreads();

    float wreg[16];
#pragma unroll
    for (int i = 0; i < 8; i++) {
        float2 wv = *(const float2*)&was_s[2 * (lane + 32 * i)];
        wreg[2 * i] = wv.x;
        wreg[2 * i + 1] = wv.y;
    }
    uint64_t ps[4] = {0ull, 0ull, 0ull, 0ull};
#pragma unroll 1
    for (int pq = w; pq < 256; pq += 8) {
        uint64_t sc[4] = {0ull, 0ull, 0ull, 0ull};
        const float2* fr = (const float2*)(g_fp + ((size_t)b * PP + pq) * AA);
#pragma unroll
        for (int i = 0; i < 8; i++) {
            int a2 = lane + 32 * i;
            float2 fv = fr[a2];
            ulonglong2 q0 = *(const ulonglong2*)&spp[0 * 512 + 2 * a2];
            ulonglong2 q1 = *(const ulonglong2*)&spp[1 * 512 + 2 * a2];
            ulonglong2 q2 = *(const ulonglong2*)&spp[2 * 512 + 2 * a2];
            ulonglong2 q3 = *(const ulonglong2*)&spp[3 * 512 + 2 * a2];
            uint64_t wp0, wp1, th;
            PACK2(wp0, wreg[2 * i]);
            PACK2(wp1, wreg[2 * i + 1]);
            uint32_t tl, th2;
            tl = __float_as_uint(tanh_fast(fv.x + u64lo(q0.x)));
            th2 = __float_as_uint(tanh_fast(fv.x + u64hi(q0.x)));
            th = (uint64_t)tl | ((uint64_t)th2 << 32); FMA2(sc[0], th, wp0);
            tl = __float_as_uint(tanh_fast(fv.x + u64lo(q1.x)));
            th2 = __float_as_uint(tanh_fast(fv.x + u64hi(q1.x)));
            th = (uint64_t)tl | ((uint64_t)th2 << 32); FMA2(sc[1], th, wp0);
            tl = __float_as_uint(tanh_fast(fv.x + u64lo(q2.x)));
            th2 = __float_as_uint(tanh_fast(fv.x + u64hi(q2.x)));
            th = (uint64_t)tl | ((uint64_t)th2 << 32); FMA2(sc[2], th, wp0);
            tl = __float_as_uint(tanh_fast(fv.x + u64lo(q3.x)));
            th2 = __float_as_uint(tanh_fast(fv.x + u64hi(q3.x)));
            th = (uint64_t)tl | ((uint64_t)th2 << 32); FMA2(sc[3], th, wp0);
            tl = __float_as_uint(tanh_fast(fv.y + u64lo(q0.y)));
            th2 = __float_as_uint(tanh_fast(fv.y + u64hi(q0.y)));
            th = (uint64_t)tl | ((uint64_t)th2 << 32); FMA2(sc[0], th, wp1);
            tl = __float_as_uint(tanh_fast(fv.y + u64lo(q1.y)));
            th2 = __float_as_uint(tanh_fast(fv.y + u64hi(q1.y)));
            th = (uint64_t)tl | ((uint64_t)th2 << 32); FMA2(sc[1], th, wp1);
            tl = __float_as_uint(tanh_fast(fv.y + u64lo(q2.y)));
            th2 = __float_as_uint(tanh_fast(fv.y + u64hi(q2.y)));
            th = (uint64_t)tl | ((uint64_t)th2 << 32); FMA2(sc[2], th, wp1);
            tl = __float_as_uint(tanh_fast(fv.y + u64lo(q3.y)));
            th2 = __float_as_uint(tanh_fast(fv.y + u64hi(q3.y)));
            th = (uint64_t)tl | ((uint64_t)th2 << 32); FMA2(sc[3], th, wp1);
        }
#pragma unroll
        for (int tp = 0; tp < 4; tp++) sc[tp] = wredsum2(sc[tp]);
        if (lane == 0) {
#pragma unroll
            for (int tp = 0; tp < 4; tp++) {
                float e0 = __expf(u64lo(sc[tp]));
                float e1 = __expf(u64hi(sc[tp]));
                attp[tp * 256 + pq] = make_float2(e0, e1);
                uint64_t ev = (uint64_t)__float_as_uint(e0) | ((uint64_t)__float_as_uint(e1) << 32);
                asm("add.rn.f32x2 %0, %0, %1;" : "+l"(ps[tp]) : "l"(ev));
            }
        }
    }
    if (lane == 0) {
#pragma unroll
        for (int tp = 0; tp < 4; tp++)
            red8p[w * 4 + tp] = make_float2(u64lo(ps[tp]), u64hi(ps[tp]));
    }
    __syncthreads();
    if (tid < 4) {
        float sx = 0.f, sy = 0.f;
#pragma unroll
        for (int ww = 0; ww < 8; ww++) {
            float2 v = red8p[ww * 4 + tid];
            sx += v.x; sy += v.y;
        }
        sinvp[tid] = make_float2(1.f / sx, 1.f / sy);
    }
    __syncthreads();
    for (int pq = tid; pq < 256; pq += 256) {
#pragma unroll
        for (int tp = 0; tp < 4; tp++) {
            float2 v = attp[tp * 256 + pq];
            float2 s = sinvp[tp];
            attp[tp * 256 + pq] = make_float2(v.x * s.x, v.y * s.y);
        }
    }
    __syncthreads();

#pragma unroll 1
    for (int c = w; c < 512; c += 8) {
        uint64_t gc[4] = {0ull, 0ull, 0ull, 0ull};
        const float2* fr = (const float2*)(feat + ((size_t)b * CF + c) * PP);
#pragma unroll
        for (int i = 0; i < 4; i++) {
            int p2 = lane + 32 * i;
            float2 fv = fr[p2];
            uint64_t fp0, fp1;
            PACK2(fp0, fv.x);
            PACK2(fp1, fv.y);
#pragma unroll
            for (int tp = 0; tp < 4; tp++) {
                ulonglong2 aq = *(const ulonglong2*)&attp[tp * 256 + 2 * p2];
                FMA2(gc[tp], aq.x, fp0);
                FMA2(gc[tp], aq.y, fp1);
            }
        }
#pragma unroll
        for (int tp = 0; tp < 4; tp++) gc[tp] = wredsum2(gc[tp]);
        if (lane == 0) {
#pragma unroll
            for (int tp = 0; tp < 4; tp++)
                glp[tp * 512 + c] = make_float2(u64lo(gc[tp]), u64hi(gc[tp]));
        }
    }
    __syncthreads();

#pragma unroll 1
    for (int v = w; v < VV1; v += 8) {
        uint64_t lg[4] = {0ull, 0ull, 0ull, 0ull};
        const float2* wr = (const float2*)(Wout + (size_t)v * 1024);
#pragma unroll
        for (int i = 0; i < 16; i++) {
            int k2 = lane + 32 * i;
            float2 wv = wr[k2];
            const float2* plane = (i < 8) ? h1p : glp;
            int kk = (i < 8) ? (2 * k2) : (2 * (k2 - 256));
            uint64_t wp0, wp1;
            PACK2(wp0, wv.x);
            PACK2(wp1, wv.y);
#pragma unroll
            for (int tp = 0; tp < 4; tp++) {
                ulonglong2 hq = *(const ulonglong2*)&plane[tp * 512 + kk];
                FMA2(lg[tp], hq.x, wp0);
                FMA2(lg[tp], hq.y, wp1);
            }
        }
#pragma unroll
        for (int tp = 0; tp < 4; tp++) lg[tp] = wredsum2(lg[tp]);
        if (lane == 0) {
            float bv = bout[v];
#pragma unroll
            for (int tp = 0; tp < 4; tp++) {
                int ja = 2 * tp, jb = 2 * tp + 1;
                if (ja < nt) out[((size_t)b * NSTEPS + t0 + ja) * VV1 + v] = u64lo(lg[tp]) + bv;
                if (jb < nt) out[((size_t)b * NSTEPS + t0 + jb) * VV1 + v] = u64hi(lg[tp]) + bv;
            }
        }
    }
}

// ---------------- launch ----------------
extern "C" void kernel_launch(void* const* d_in, const int* in_sizes, int n_in,
                              void* d_out, int out_size) {
    (void)in_sizes; (void)n_in; (void)out_size;
    const float* features = (const float*)d_in[0];
    const int*   gt       = (const int*)d_in[2];
    const float* W_feat   = (const float*)d_in[3];
    const float* b_feat   = (const float*)d_in[4];
    const float* W_state  = (const float*)d_in[5];
    const float* w_att    = (const float*)d_in[6];
    const float* W_embed  = (const float*)d_in[7];
    const float* wih0     = (const float*)d_in[8];
    const float* whh0     = (const float*)d_in[9];
    const float* bih0     = (const float*)d_in[10];
    const float* bhh0     = (const float*)d_in[11];
    const float* wih1     = (const float*)d_in[12];
    const float* whh1     = (const float*)d_in[13];
    const float* bih1     = (const float*)d_in[14];
    const float* bhh1     = (const float*)d_in[15];
    const float* W_out    = (const float*)d_in[16];
    const float* b_out    = (const float*)d_in[17];
    float* out = (float*)d_out;

    static const int DEC_SMEM = (24576 + 16512 + 2112 + 2112 + 32) * 4;
    static const int XG_SMEM = 2 * CSTAGE + 1024;
    cudaFuncSetAttribute(k_lstm, cudaFuncAttributeMaxDynamicSharedMemorySize, DEC_SMEM);
    cudaFuncSetAttribute(k_conv_mma, cudaFuncAttributeMaxDynamicSharedMemorySize, CONV_SMEM);
    cudaFuncSetAttribute(k_xgemm, cudaFuncAttributeMaxDynamicSharedMemorySize, XG_SMEM);
    cudaFuncSetAttribute(k_attn, cudaFuncAttributeMaxDynamicSharedMemorySize, ATT_SMEM);

    k_init<<<4096, 256>>>(gt, W_embed, wih0);
    k_prep_feat<<<dim3(8, 16, 32), dim3(32, 32)>>>(features);
    k_prep_w<<<512, 256>>>(W_feat);
    k_conv_mma<<<256, 256, CONV_SMEM>>>(b_feat);
    k_xgemm<<<128, 256, XG_SMEM>>>();
    k_lstm<<<NBLK, NTHR, DEC_SMEM>>>(whh0, bih0, bhh0,
                                     wih1, whh1, bih1, bhh1);
    k_attn<<<dim3(32, 4), 256, ATT_SMEM>>>(features, W_state, w_att, W_out, b_out, out);
}

// round 16
// speedup vs baseline: 1.0385x; 1.0385x over previous
#include <cuda_runtime.h>
#include <cuda_bf16.h>
#include <cstdint>

#define BB      32
#define HH      8
#define WW2     32
#define PP      256
#define CF      512
#define AA      512
#define RR      512
#define VV1     111
#define NSTEPS  31
#define NBLK    128
#define NTHR    512

#define PY      10
#define PX      34

// ---------------- device scratch ----------------
__device__ float g_fp[(size_t)BB * PP * AA];
__device__ float g_h0[2][BB * RR];
__device__ float g_h1h[32][BB * RR];    // h1 history: slot t+1 = h1(t); slot 0 = zeros
__device__ float g_c0[BB * RR];
__device__ float g_c1[BB * RR];
__device__ float g_xg[(size_t)2048 * 1024];   // precomputed wih0 @ x : [row][t*32+b]
__device__ unsigned g_arr[NBLK];
__device__ unsigned g_rel[NBLK];

__device__ __nv_bfloat16 g_fa_hi[(size_t)BB * PY * PX * CF];
__device__ __nv_bfloat16 g_fa_lo[(size_t)BB * PY * PX * CF];
__device__ __nv_bfloat16 g_wb_hi[(size_t)9 * AA * CF];
__device__ __nv_bfloat16 g_wb_lo[(size_t)9 * AA * CF];
__device__ __nv_bfloat16 g_wA_hi[(size_t)2048 * 512];
__device__ __nv_bfloat16 g_wA_lo[(size_t)2048 * 512];
__device__ __nv_bfloat16 g_xb_hi[(size_t)1024 * 512];
__device__ __nv_bfloat16 g_xb_lo[(size_t)1024 * 512];

__device__ __forceinline__ float tanh_fast(float x) {
    float y;
    asm("tanh.approx.f32 %0, %1;" : "=f"(y) : "f"(x));
    return y;
}

// store-based barrier: private arrival slots, block 0 polls + fans out releases.
__device__ __forceinline__ void grid_bar(int blk, unsigned ep) {
    __syncthreads();
    if (blk == 0) {
        if (threadIdx.x == 0) __threadfence();
        if (threadIdx.x > 0 && threadIdx.x < NBLK) {
            while (*(volatile unsigned*)&g_arr[threadIdx.x] < ep) { }
        }
        __syncthreads();
        if (threadIdx.x == 0) __threadfence();
        __syncthreads();
        if (threadIdx.x > 0 && threadIdx.x < NBLK)
            *(volatile unsigned*)&g_rel[threadIdx.x] = ep;
    } else {
        if (threadIdx.x == 0) {
            __threadfence();
            *(volatile unsigned*)&g_arr[blk] = ep;
            while (*(volatile unsigned*)&g_rel[blk] < ep) { }
            __threadfence();
        }
    }
    __syncthreads();
}

__device__ __forceinline__ uint32_t smem_u32(const void* p) {
    uint32_t a;
    asm("{ .reg .u64 t; cvta.to.shared.u64 t, %1; cvt.u32.u64 %0, t; }" : "=r"(a) : "l"(p));
    return a;
}

#define SW128(o) ((o) ^ (((o) >> 3) & 0x70))

__device__ __forceinline__ void cp16(uint32_t s, const void* g) {
    asm volatile("cp.async.cg.shared.global [%0], [%1], 16;" :: "r"(s), "l"(g) : "memory");
}

#define LDSM4(r, addr) \
    asm volatile("ldmatrix.sync.aligned.m8n8.x4.shared.b16 {%0,%1,%2,%3}, [%4];" \
        : "=r"((r)[0]), "=r"((r)[1]), "=r"((r)[2]), "=r"((r)[3]) : "r"(addr))

#define MMA16816(d, a, b) \
    asm volatile("mma.sync.aligned.m16n8k16.row.col.f32.bf16.bf16.f32 " \
        "{%0,%1,%2,%3}, {%4,%5,%6,%7}, {%8,%9}, {%0,%1,%2,%3};" \
        : "+f"((d)[0]), "+f"((d)[1]), "+f"((d)[2]), "+f"((d)[3]) \
        : "r"((a)[0]), "r"((a)[1]), "r"((a)[2]), "r"((a)[3]), "r"((b)[0]), "r"((b)[1]))

#define FMA2(acc, w, aa) \
    asm("fma.rn.f32x2 %0, %1, %2, %0;" : "+l"(acc) : "l"(w), "l"(aa))

#define PACK2(aa, f) \
    do { uint32_t _u = __float_as_uint(f); \
         asm("mov.b64 %0, {%1, %1};" : "=l"(aa) : "r"(_u)); } while (0)

__device__ __forceinline__ unsigned long long wredsum2(unsigned long long v) {
#pragma unroll
    for (int o = 16; o; o >>= 1) {
        unsigned long long u = __shfl_xor_sync(0xffffffffu, v, o);
        asm("add.rn.f32x2 %0, %0, %1;" : "+l"(v) : "l"(u));
    }
    return v;
}

__device__ __forceinline__ float u64lo(unsigned long long v) { return __uint_as_float((uint32_t)v); }
__device__ __forceinline__ float u64hi(unsigned long long v) { return __uint_as_float((uint32_t)(v >> 32)); }

// ---------------- merged init ----------------
__global__ void k_init(const int* __restrict__ gt, const float* __restrict__ W_embed,
                       const float* __restrict__ wih0) {
    int idx = blockIdx.x * 256 + threadIdx.x;        // 4096 x 256 = 1048576
    if (idx < NBLK) { g_arr[idx] = 0; g_rel[idx] = 0; }
    if (idx < BB * RR) {
        g_h0[0][idx] = 0.f;
        g_h0[1][idx] = 0.f;
        g_h1h[0][idx] = 0.f;
        g_c0[idx] = 0.f;
        g_c1[idx] = 0.f;
    }
    if (idx < 1024 * 512) {
        int n = idx >> 9, r = idx & 511;
        int t = n >> 5, b = n & 31;
        float v = 0.f;
        if (t >= 1 && t <= 30) {
            int g = gt[b * NSTEPS + t - 1];
            v = W_embed[r * VV1 + g];
        }
        __nv_bfloat16 hi = __float2bfloat16(v);
        __nv_bfloat16 lo = __float2bfloat16(v - __bfloat162float(hi));
        g_xb_hi[idx] = hi;
        g_xb_lo[idx] = lo;
    }
    {
        float v = wih0[idx];
        __nv_bfloat16 hi = __float2bfloat16(v);
        __nv_bfloat16 lo = __float2bfloat16(v - __bfloat162float(hi));
        g_wA_hi[idx] = hi;
        g_wA_lo[idx] = lo;
    }
    {
        size_t n = (size_t)BB * PY * PX * CF / 2;
        uint32_t* a = (uint32_t*)g_fa_hi;
        uint32_t* b = (uint32_t*)g_fa_lo;
        for (size_t i = idx; i < n; i += (size_t)4096 * 256) {
            a[i] = 0u;
            b[i] = 0u;
        }
    }
}

// ---------------- conv prep kernels ----------------
__global__ void k_prep_feat(const float* __restrict__ feat) {
    __shared__ float sm[32][33];
    int pblk = blockIdx.x, c0 = blockIdx.y * 32, b = blockIdx.z;
    int tx = threadIdx.x, ty = threadIdx.y;
    sm[ty][tx] = feat[((size_t)b * CF + c0 + ty) * PP + pblk * 32 + tx];
    __syncthreads();
    int c = c0 + tx;
    float v = sm[tx][ty];
    __nv_bfloat16 hi = __float2bfloat16(v);
    __nv_bfloat16 lo = __float2bfloat16(v - __bfloat162float(hi));
    size_t o = (((size_t)b * PY + (pblk + 1)) * PX + (ty + 1)) * CF + c;
    g_fa_hi[o] = hi;
    g_fa_lo[o] = lo;
}

__global__ void k_prep_w(const float* __restrict__ Wf) {
    __shared__ float wrow[CF * 9];
    int a = blockIdx.x, tid = threadIdx.x;
    for (int i = tid; i < CF * 9; i += 256) wrow[i] = Wf[(size_t)a * CF * 9 + i];
    __syncthreads();
    for (int tap = 0; tap < 9; tap++) {
        for (int c = tid; c < CF; c += 256) {
            float v = wrow[c * 9 + tap];
            __nv_bfloat16 hi = __float2bfloat16(v);
            __nv_bfloat16 lo = __float2bfloat16(v - __bfloat162float(hi));
            size_t o = ((size_t)tap * AA + a) * CF + c;
            g_wb_hi[o] = hi;
            g_wb_lo[o] = lo;
        }
    }
}

// ---------------- tensor-core conv with HALO-REUSE A staging (fixed coverage) ----------
// R7 tiling (256 CTAs, M=128, N=128, warp 64x32) but A padded tile (6 rows x 34 cols
// = 204 positions x 64 ch) staged ONCE per channel chunk; taps use shifted per-lane
// ldmatrix addresses. FIX vs R15: stage_A q<8 (128 B/row), stage_B q<4 (full rows).
#define A_LO_OFF 26624            // 204*128 = 26112 -> pad to 26*1024
#define B_BASE   53248            // 2*26624
#define B_STG    32768            // per stage: hi 16K | lo 16K
#define CONV_SMEM (B_BASE + 2 * B_STG + 1024)

__global__ void __launch_bounds__(256) k_conv_mma(const float* __restrict__ bfeat) {
    extern __shared__ char dsm[];
    uint32_t sb = (smem_u32(dsm) + 1023) & ~1023u;
    uint32_t Ahi = sb, Alo = sb + A_LO_OFF, Bb0 = sb + B_BASE;

    int tid = threadIdx.x;
    int lane = tid & 31, wid = tid >> 5;
    int warp_m = wid & 1, warp_n = wid >> 1;

    int Ntile = blockIdx.x & 3;
    int Mtile = blockIdx.x >> 2;
    int n0 = Ntile * 128;
    int b = Mtile >> 1;
    int r0 = (Mtile & 1) * 4;        // padded row base of this M-tile

    int row_l = lane & 15, kh_a = lane >> 4;
    int base_pi[4];
#pragma unroll
    for (int mi = 0; mi < 4; mi++) {
        int lp = warp_m * 64 + mi * 16 + row_l;
        base_pi[mi] = (lp >> 5) * 34 + (lp & 31);
    }

    int kh_b = (lane >> 3) & 1;
    int n_l = (lane & 7) + ((lane >> 4) << 3);
    uint32_t boff[2], bxorm[2];
#pragma unroll
    for (int np = 0; np < 2; np++) {
        int n = warp_n * 32 + np * 16 + n_l;
        boff[np] = n * 128;
        bxorm[np] = (n & 7) << 4;
    }

    float acc[4][4][4];
#pragma unroll
    for (int mi = 0; mi < 4; mi++)
#pragma unroll
        for (int ni = 0; ni < 4; ni++)
#pragma unroll
            for (int q = 0; q < 4; q++) acc[mi][ni][q] = 0.f;

    // A loader: 204 rows x 128 B (hi+lo), once per chunk; one thread per row, 8x16B.
    auto stage_A = [&](int c) {
        if (tid < 204) {
            int rr = tid / 34, xx = tid - rr * 34;
            size_t ga = (((size_t)b * PY + r0 + rr) * PX + xx) * CF + c * 64;
            const char* ph = (const char*)(g_fa_hi + ga);
            const char* pl = (const char*)(g_fa_lo + ga);
#pragma unroll
            for (int q = 0; q < 8; q++) {
                uint32_t off = SW128((uint32_t)tid * 128 + q * 16);
                cp16(Ahi + off, ph + q * 16);
                cp16(Alo + off, pl + q * 16);
            }
        }
    };
    // B loader: 128 rows x 128 B (hi+lo); 2 threads per row, 4x16B each.
    int brow = tid >> 1, bhalf = tid & 1;
    auto stage_B = [&](int tap, int c, int st) {
        size_t gb = ((size_t)tap * AA + n0 + brow) * CF + c * 64 + bhalf * 32;
        const char* ph = (const char*)(g_wb_hi + gb);
        const char* pl = (const char*)(g_wb_lo + gb);
        uint32_t bs = Bb0 + st * B_STG;
#pragma unroll
        for (int q = 0; q < 4; q++) {
            uint32_t off = SW128((uint32_t)brow * 128 + bhalf * 64 + q * 16);
            cp16(bs + off, ph + q * 16);
            cp16(bs + 16384 + off, pl + q * 16);
        }
    };

    stage_A(0);
    stage_B(0, 0, 0);
    asm volatile("cp.async.commit_group;" ::: "memory");

    int c = 0, tap = 0;
#pragma unroll 1
    for (int it = 0; it < 72; it++) {
        int st = it & 1;
        asm volatile("cp.async.wait_group 0;" ::: "memory");
        __syncthreads();
        bool lastTap = (tap == 8);
        if (!lastTap) {
            stage_B(tap + 1, c, st ^ 1);
            asm volatile("cp.async.commit_group;" ::: "memory");
        }

        int ky = tap / 3, kx = tap - ky * 3;
        int dpi = ky * 34 + kx;
        uint32_t Bb = Bb0 + st * B_STG;
#pragma unroll
        for (int ks = 0; ks < 4; ks++) {
            uint32_t ahi[4][4], alo[4][4], bhi[4][2], blo[4][2];
            uint32_t kca = ks * 32 + kh_a * 16;
            uint32_t kcb = ks * 32 + kh_b * 16;
#pragma unroll
            for (int mi = 0; mi < 4; mi++) {
                int pi = base_pi[mi] + dpi;
                uint32_t ad = Ahi + (uint32_t)pi * 128 + (kca ^ ((pi & 7) << 4));
                LDSM4(ahi[mi], ad);
                LDSM4(alo[mi], ad + A_LO_OFF);
            }
#pragma unroll
            for (int np = 0; np < 2; np++) {
                uint32_t bd = Bb + boff[np] + (kcb ^ bxorm[np]);
                uint32_t r[4];
                LDSM4(r, bd);
                bhi[np * 2][0] = r[0]; bhi[np * 2][1] = r[1];
                bhi[np * 2 + 1][0] = r[2]; bhi[np * 2 + 1][1] = r[3];
                LDSM4(r, bd + 16384);
                blo[np * 2][0] = r[0]; blo[np * 2][1] = r[1];
                blo[np * 2 + 1][0] = r[2]; blo[np * 2 + 1][1] = r[3];
            }
#pragma unroll
            for (int mi = 0; mi < 4; mi++)
#pragma unroll
                for (int ni = 0; ni < 4; ni++) {
                    MMA16816(acc[mi][ni], ahi[mi], bhi[ni]);
                    MMA16816(acc[mi][ni], ahi[mi], blo[ni]);
                    MMA16816(acc[mi][ni], alo[mi], bhi[ni]);
                }
        }

        if (lastTap) {
            tap = 0; c++;
            if (c < 8) {
                __syncthreads();           // all reads of A buffer complete
                stage_A(c);
                stage_B(0, c, st ^ 1);
                asm volatile("cp.async.commit_group;" ::: "memory");
            }
        } else {
            tap++;
        }
    }

    int rgrp = lane >> 2, cpair = (lane & 3) * 2;
    float bs0[4], bs1[4];
#pragma unroll
    for (int ni = 0; ni < 4; ni++) {
        int a = n0 + warp_n * 32 + ni * 8 + cpair;
        bs0[ni] = bfeat[a];
        bs1[ni] = bfeat[a + 1];
    }
#pragma unroll
    for (int mi = 0; mi < 4; mi++) {
#pragma unroll
        for (int h = 0; h < 2; h++) {
            int m = Mtile * 128 + warp_m * 64 + mi * 16 + rgrp + h * 8;
            int obb = m >> 8, op = m & 255;
            float* dst = g_fp + ((size_t)obb * PP + op) * AA + n0 + warp_n * 32;
#pragma unroll
            for (int ni = 0; ni < 4; ni++) {
                float2 v;
                v.x = acc[mi][ni][h * 2 + 0] + bs0[ni];
                v.y = acc[mi][ni][h * 2 + 1] + bs1[ni];
                *(float2*)(dst + ni * 8 + cpair) = v;
            }
        }
    }
}

// ---------------- xg GEMM: xg[2048 x 1024] = wih0 @ x^T (bf16 3-term) ----------------
#define CSTAGE 65536
__global__ void __launch_bounds__(256) k_xgemm() {
    extern __shared__ char dsm[];
    uint32_t sb = (smem_u32(dsm) + 1023) & ~1023u;

    int tid = threadIdx.x;
    int lane = tid & 31, wid = tid >> 5;
    int warp_m = wid & 1, warp_n = wid >> 1;

    int Mtile = blockIdx.x >> 3;
    int Ntile = blockIdx.x & 7;
    int m0 = Mtile * 128, n0 = Ntile * 128;

    int arow = tid >> 1, ahalf = tid & 1;

    int kh_a = lane >> 4;
    int row_l = lane & 15;
    uint32_t aoff[4], axorm[4];
#pragma unroll
    for (int mi = 0; mi < 4; mi++) {
        int row = warp_m * 64 + mi * 16 + row_l;
        aoff[mi] = row * 128;
        axorm[mi] = (row & 7) << 4;
    }
    int kh_b = (lane >> 3) & 1;
    int n_l = (lane & 7) + ((lane >> 4) << 3);
    uint32_t boff[2], bxorm[2];
#pragma unroll
    for (int np = 0; np < 2; np++) {
        int n = warp_n * 32 + np * 16 + n_l;
        boff[np] = n * 128;
        bxorm[np] = (n & 7) << 4;
    }

    float acc[4][4][4];
#pragma unroll
    for (int mi = 0; mi < 4; mi++)
#pragma unroll
        for (int ni = 0; ni < 4; ni++)
#pragma unroll
            for (int q = 0; q < 4; q++) acc[mi][ni][q] = 0.f;

    auto issue_chunk = [&](int cblk, int st) {
        uint32_t sbase = sb + st * CSTAGE;
        size_t ga = (size_t)(m0 + arow) * 512 + cblk * 64 + ahalf * 32;
        size_t gb = (size_t)(n0 + arow) * 512 + cblk * 64 + ahalf * 32;
        const char* pahi = (const char*)(g_wA_hi + ga);
        const char* palo = (const char*)(g_wA_lo + ga);
        const char* pbhi = (const char*)(g_xb_hi + gb);
        const char* pblo = (const char*)(g_xb_lo + gb);
#pragma unroll
        for (int q = 0; q < 4; q++) {
            uint32_t off = arow * 128 + ahalf * 64 + q * 16;
            uint32_t sw = SW128(off);
            cp16(sbase + sw,          pahi + q * 16);
            cp16(sbase + 16384 + sw,  palo + q * 16);
            cp16(sbase + 32768 + sw,  pbhi + q * 16);
            cp16(sbase + 49152 + sw,  pblo + q * 16);
        }
        asm volatile("cp.async.commit_group;" ::: "memory");
    };

    issue_chunk(0, 0);

#pragma unroll 1
    for (int it = 0; it < 8; it++) {
        int st = it & 1;
        asm volatile("cp.async.wait_group 0;" ::: "memory");
        __syncthreads();
        if (it + 1 < 8) issue_chunk(it + 1, st ^ 1);

        uint32_t Ab = sb + st * CSTAGE;
        uint32_t Bb = Ab + 32768;
#pragma unroll
        for (int ks = 0; ks < 4; ks++) {
            uint32_t ahi[4][4], alo[4][4], bhi[4][2], blo[4][2];
            uint32_t kca = ks * 32 + kh_a * 16;
            uint32_t kcb = ks * 32 + kh_b * 16;
#pragma unroll
            for (int mi = 0; mi < 4; mi++) {
                uint32_t ad = Ab + aoff[mi] + (kca ^ axorm[mi]);
                LDSM4(ahi[mi], ad);
                LDSM4(alo[mi], ad + 16384);
            }
#pragma unroll
            for (int np = 0; np < 2; np++) {
                uint32_t bd = Bb + boff[np] + (kcb ^ bxorm[np]);
                uint32_t r[4];
                LDSM4(r, bd);
                bhi[np * 2][0] = r[0]; bhi[np * 2][1] = r[1];
                bhi[np * 2 + 1][0] = r[2]; bhi[np * 2 + 1][1] = r[3];
                LDSM4(r, bd + 16384);
                blo[np * 2][0] = r[0]; blo[np * 2][1] = r[1];
                blo[np * 2 + 1][0] = r[2]; blo[np * 2 + 1][1] = r[3];
            }
#pragma unroll
            for (int mi = 0; mi < 4; mi++)
#pragma unroll
                for (int ni = 0; ni < 4; ni++) {
                    MMA16816(acc[mi][ni], ahi[mi], bhi[ni]);
                    MMA16816(acc[mi][ni], ahi[mi], blo[ni]);
                    MMA16816(acc[mi][ni], alo[mi], bhi[ni]);
                }
        }
    }

    int rgrp = lane >> 2, cpair = (lane & 3) * 2;
#pragma unroll
    for (int mi = 0; mi < 4; mi++) {
#pragma unroll
        for (int h = 0; h < 2; h++) {
            int m = m0 + warp_m * 64 + mi * 16 + rgrp + h * 8;
            float* dst = g_xg + (size_t)m * 1024 + n0 + warp_n * 32;
#pragma unroll
            for (int ni = 0; ni < 4; ni++) {
                float2 v;
                v.x = acc[mi][ni][h * 2 + 0];
                v.y = acc[mi][ni][h * 2 + 1];
                *(float2*)(dst + ni * 8 + cpair) = v;
            }
        }
    }
}

// ---------------- persistent LSTM (R13: 4-way k-split, merged dual epilogue) --------
__global__ void __launch_bounds__(NTHR) k_lstm(
    const float* __restrict__ whh0,
    const float* __restrict__ bih0, const float* __restrict__ bhh0,
    const float* __restrict__ wih1, const float* __restrict__ whh1,
    const float* __restrict__ bih1, const float* __restrict__ bhh1)
{
    extern __shared__ float smdyn[];
    float* Wsm   = smdyn;
    float* acts  = Wsm + 24576;
    float* gredA = acts + 16512;
    float* gredB = gredA + 2112;
    float* bsum  = gredB + 2112;

    int tid = threadIdx.x, blk = blockIdx.x;
    int j0 = blk * 4;
    int lane = tid & 31;
    int rg = (tid >> 5) & 3;
    int ksp = tid >> 7;

    {
        const float* srcs[3] = {wih1, whh0, whh1};
        int pr = (tid >> 5) & 7;
        int half = tid >> 8;
        int lr0 = 2 * pr, lr1 = 2 * pr + 1;
        int r0 = (lr0 & 3) * 512 + j0 + (lr0 >> 2);
        int r1 = (lr1 & 3) * 512 + j0 + (lr1 >> 2);
#pragma unroll 1
        for (int rr2 = 0; rr2 < 3; rr2++) {
            const float* W = srcs[rr2];
            float* dst = Wsm + rr2 * 8192 + pr * 1024;
#pragma unroll
            for (int q = 0; q < 8; q++) {
                int k = (half * 8 + q) * 32 + lane;
                dst[2 * k]     = W[(size_t)r0 * 512 + k];
                dst[2 * k + 1] = W[(size_t)r1 * 512 + k];
            }
        }
    }
    if (tid < 32) {
        int cell = tid >> 4, lr = tid & 15;
        int row = (lr & 3) * 512 + j0 + (lr >> 2);
        bsum[tid] = (cell ? (bih1[row] + bhh1[row]) : (bih0[row] + bhh0[row]));
    }
    __syncthreads();

    uint32_t acts_b = smem_u32(acts);
    int sb = tid >> 4, smi = tid & 15;

    auto stage = [&](const float* src) {
        __syncthreads();
        uint32_t dstb = acts_b + sb * 516 * 4 + smi * 16;
        const float* gsrc = src + sb * 512 + smi * 4;
#pragma unroll
        for (int q = 0; q < 8; q++) cp16(dstb + q * 256, gsrc + q * 64);
        asm volatile("cp.async.commit_group;" ::: "memory");
        asm volatile("cp.async.wait_group 0;" ::: "memory");
        __syncthreads();
    };

    auto accum = [&](int regionBase, uint64_t& a0, uint64_t& a1) {
        const float* wp0 = Wsm + regionBase + (rg * 2) * 1024 + ksp * 256;
        const float* wp1 = wp0 + 1024;
        const float* ab = acts + lane * 516 + ksp * 128;
#pragma unroll 8
        for (int kk = 0; kk < 128; kk += 4) {
            float4 a4 = *(const float4*)&ab[kk];
            ulonglong2 wA = *(const ulonglong2*)&wp0[kk * 2];
            ulonglong2 wB = *(const ulonglong2*)&wp0[kk * 2 + 4];
            ulonglong2 wC = *(const ulonglong2*)&wp1[kk * 2];
            ulonglong2 wD = *(const ulonglong2*)&wp1[kk * 2 + 4];
            uint64_t aa;
            PACK2(aa, a4.x);
            FMA2(a0, wA.x, aa); FMA2(a1, wC.x, aa);
            PACK2(aa, a4.y);
            FMA2(a0, wA.y, aa); FMA2(a1, wC.y, aa);
            PACK2(aa, a4.z);
            FMA2(a0, wB.x, aa); FMA2(a1, wD.x, aa);
            PACK2(aa, a4.w);
            FMA2(a0, wB.y, aa); FMA2(a1, wD.y, aa);
        }
    };

    auto put_gred = [&](float* gr0, uint64_t a0, uint64_t a1) {
        float* gr = gr0 + ksp * 528 + (rg * 4) * 33 + lane;
        gr[0]  = u64lo(a0);
        gr[33] = u64hi(a0);
        gr[66] = u64lo(a1);
        gr[99] = u64hi(a1);
    };

    if (tid < 128) {
        int u = tid >> 5, b2 = tid & 31;
        float ai = g_xg[(size_t)(0 * 512 + j0 + u) * 1024 + b2] + bsum[u * 4 + 0];
        float ag = g_xg[(size_t)(2 * 512 + j0 + u) * 1024 + b2] + bsum[u * 4 + 2];
        float ao = g_xg[(size_t)(3 * 512 + j0 + u) * 1024 + b2] + bsum[u * 4 + 3];
        float si2 = 1.f / (1.f + __expf(-ai));
        float so  = 1.f / (1.f + __expf(-ao));
        float tg  = tanhf(ag);
        int o = b2 * 512 + j0 + u;
        float cn = si2 * tg;
        g_c0[o] = cn;
        g_h0[0][o] = so * tanhf(cn);
    }
    grid_bar(blk, 1);
    unsigned ep = 1;

#pragma unroll 1
    for (int t = 0; t < NSTEPS; t++) {
        int p = t & 1;
        bool lastt = (t == NSTEPS - 1);

        float xr0 = 0.f, xr1 = 0.f, xr2 = 0.f, xr3 = 0.f;
        if (tid >= 128 && tid < 256 && !lastt) {
            int u = (tid - 128) >> 5, b2 = tid & 31;
            size_t cb = (size_t)(t + 1) * 32 + b2;
            xr0 = __ldg(&g_xg[(size_t)(0 * 512 + j0 + u) * 1024 + cb]);
            xr1 = __ldg(&g_xg[(size_t)(1 * 512 + j0 + u) * 1024 + cb]);
            xr2 = __ldg(&g_xg[(size_t)(2 * 512 + j0 + u) * 1024 + cb]);
            xr3 = __ldg(&g_xg[(size_t)(3 * 512 + j0 + u) * 1024 + cb]);
        }

        uint64_t c1a0 = 0ull, c1a1 = 0ull;
        uint64_t c0a0 = 0ull, c0a1 = 0ull;

        stage(g_h0[p]);
        accum(0, c1a0, c1a1);
        if (!lastt) accum(8192, c0a0, c0a1);

        stage(g_h1h[t]);
        accum(16384, c1a0, c1a1);

        put_gred(gredA, c1a0, c1a1);
        if (!lastt) put_gred(gredB, c0a0, c0a1);
        __syncthreads();
        if (tid < 128) {
            int u = tid >> 5, b2 = tid & 31;
            int lrb = u * 4;
            float ai = gredA[(lrb + 0) * 33 + b2] + gredA[528 + (lrb + 0) * 33 + b2]
                     + gredA[1056 + (lrb + 0) * 33 + b2] + gredA[1584 + (lrb + 0) * 33 + b2] + bsum[16 + lrb + 0];
            float af = gredA[(lrb + 1) * 33 + b2] + gredA[528 + (lrb + 1) * 33 + b2]
                     + gredA[1056 + (lrb + 1) * 33 + b2] + gredA[1584 + (lrb + 1) * 33 + b2] + bsum[16 + lrb + 1];
            float ag = gredA[(lrb + 2) * 33 + b2] + gredA[528 + (lrb + 2) * 33 + b2]
                     + gredA[1056 + (lrb + 2) * 33 + b2] + gredA[1584 + (lrb + 2) * 33 + b2] + bsum[16 + lrb + 2];
            float ao = gredA[(lrb + 3) * 33 + b2] + gredA[528 + (lrb + 3) * 33 + b2]
                     + gredA[1056 + (lrb + 3) * 33 + b2] + gredA[1584 + (lrb + 3) * 33 + b2] + bsum[16 + lrb + 3];
            float si2 = 1.f / (1.f + __expf(-ai));
            float sf  = 1.f / (1.f + __expf(-af));
            float so  = 1.f / (1.f + __expf(-ao));
            float tg  = tanhf(ag);
            int o = b2 * 512 + j0 + u;
            float cn = sf * g_c1[o] + si2 * tg;
            g_c1[o] = cn;
            g_h1h[t + 1][o] = so * tanhf(cn);
        } else if (tid < 256 && !lastt) {
            int u = (tid - 128) >> 5, b2 = tid & 31;
            int lrb = u * 4;
            float ai = gredB[(lrb + 0) * 33 + b2] + gredB[528 + (lrb + 0) * 33 + b2]
                     + gredB[1056 + (lrb + 0) * 33 + b2] + gredB[1584 + (lrb + 0) * 33 + b2] + xr0 + bsum[lrb + 0];
            float af = gredB[(lrb + 1) * 33 + b2] + gredB[528 + (lrb + 1) * 33 + b2]
                     + gredB[1056 + (lrb + 1) * 33 + b2] + gredB[1584 + (lrb + 1) * 33 + b2] + xr1 + bsum[lrb + 1];
            float ag = gredB[(lrb + 2) * 33 + b2] + gredB[528 + (lrb + 2) * 33 + b2]
                     + gredB[1056 + (lrb + 2) * 33 + b2] + gredB[1584 + (lrb + 2) * 33 + b2] + xr2 + bsum[lrb + 2];
            float ao = gredB[(lrb + 3) * 33 + b2] + gredB[528 + (lrb + 3) * 33 + b2]
                     + gredB[1056 + (lrb + 3) * 33 + b2] + gredB[1584 + (lrb + 3) * 33 + b2] + xr3 + bsum[lrb + 3];
            float si2 = 1.f / (1.f + __expf(-ai));
            float sf  = 1.f / (1.f + __expf(-af));
            float so  = 1.f / (1.f + __expf(-ao));
            float tg  = tanhf(ag);
            int o = b2 * 512 + j0 + u;
            float cn = sf * g_c0[o] + si2 * tg;
            g_c0[o] = cn;
            g_h0[p ^ 1][o] = so * tanhf(cn);
        }
        grid_bar(blk, ++ep);
    }
}

// ---------------- attention + output (unchanged) ----------------
#define ATT_SMEM 59680

__global__ void __launch_bounds__(256) k_attn(
    const float* __restrict__ feat,
    const float* __restrict__ Wst, const float* __restrict__ watt,
    const float* __restrict__ Wout, const float* __restrict__ bout,
    float* __restrict__ out)
{
    extern __shared__ float asmem[];
    float2* h1p  = (float2*)asmem;
    float2* spp  = h1p + 2048;
    float2* attp = spp + 2048;
    float2* glp  = attp + 1024;
    float*  was_s = (float*)(glp + 2048);
    float2* red8p = (float2*)(was_s + 512);
    float2* sinvp = red8p + 32;

    int b = blockIdx.x, tg = blockIdx.y;
    int t0 = tg * 8;
    int nt = (t0 + 8 <= NSTEPS) ? 8 : (NSTEPS - t0);
    int tid = threadIdx.x, lane = tid & 31, w = tid >> 5;

    for (int i = tid; i < 512; i += 256) {
        was_s[i] = watt[i];
#pragma unroll
        for (int tp = 0; tp < 4; tp++) {
            int ja = 2 * tp, jb = 2 * tp + 1;
            float v0 = (ja < nt) ? g_h1h[t0 + ja + 1][b * 512 + i] : 0.f;
            float v1 = (jb < nt) ? g_h1h[t0 + jb + 1][b * 512 + i] : 0.f;
            h1p[tp * 512 + i] = make_float2(v0, v1);
        }
    }
    __syncthreads();

#pragma unroll 1
    for (int a = w; a < 512; a += 8) {
        uint64_t acc[4] = {0ull, 0ull, 0ull, 0ull};
        const float2* wr = (const float2*)(Wst + (size_t)a * 512);
#pragma unroll
        for (int i = 0; i < 8; i++) {
            int k2 = lane + 32 * i;
            float2 wv = wr[k2];
            uint64_t wp;
#pragma unroll
            for (int tp = 0; tp < 4; tp++) {
                ulonglong2 hq = *(const ulonglong2*)&h1p[tp * 512 + 2 * k2];
                PACK2(wp, wv.x); FMA2(acc[tp], hq.x, wp);
                PACK2(wp, wv.y); FMA2(acc[tp], hq.y, wp);
            }
        }
#pragma unroll
        for (int tp = 0; tp < 4; tp++) acc[tp] = wredsum2(acc[tp]);
        if (lane == 0) {
#pragma unroll
            for (int tp = 0; tp < 4; tp++)
                spp[tp * 512 + a] = make_float2(u64lo(acc[tp]), u64hi(acc[tp]));
        }
    }
    __syncthreads();

    float wreg[16];
#pragma unroll
    for (int i = 0; i < 8; i++) {
        float2 wv = *(const float2*)&was_s[2 * (lane + 32 * i)];
        wreg[2 * i] = wv.x;
        wreg[2 * i + 1] = wv.y;
    }
    uint64_t ps[4] = {0ull, 0ull, 0ull, 0ull};
#pragma unroll 1
    for (int pq = w; pq < 256; pq += 8) {
        uint64_t sc[4] = {0ull, 0ull, 0ull, 0ull};
        const float2* fr = (const float2*)(g_fp + ((size_t)b * PP + pq) * AA);
#pragma unroll
        for (int i = 0; i < 8; i++) {
            int a2 = lane + 32 * i;
            float2 fv = fr[a2];
            ulonglong2 q0 = *(const ulonglong2*)&spp[0 * 512 + 2 * a2];
            ulonglong2 q1 = *(const ulonglong2*)&spp[1 * 512 + 2 * a2];
            ulonglong2 q2 = *(const ulonglong2*)&spp[2 * 512 + 2 * a2];
            ulonglong2 q3 = *(const ulonglong2*)&spp[3 * 512 + 2 * a2];
            uint64_t wp0, wp1, th;
            PACK2(wp0, wreg[2 * i]);
            PACK2(wp1, wreg[2 * i + 1]);
            uint32_t tl, th2;
            tl = __float_as_uint(tanh_fast(fv.x + u64lo(q0.x)));
            th2 = __float_as_uint(tanh_fast(fv.x + u64hi(q0.x)));
            th = (uint64_t)tl | ((uint64_t)th2 << 32); FMA2(sc[0], th, wp0);
            tl = __float_as_uint(tanh_fast(fv.x + u64lo(q1.x)));
            th2 = __float_as_uint(tanh_fast(fv.x + u64hi(q1.x)));
            th = (uint64_t)tl | ((uint64_t)th2 << 32); FMA2(sc[1], th, wp0);
            tl = __float_as_uint(tanh_fast(fv.x + u64lo(q2.x)));
            th2 = __float_as_uint(tanh_fast(fv.x + u64hi(q2.x)));
            th = (uint64_t)tl | ((uint64_t)th2 << 32); FMA2(sc[2], th, wp0);
            tl = __float_as_uint(tanh_fast(fv.x + u64lo(q3.x)));
            th2 = __float_as_uint(tanh_fast(fv.x + u64hi(q3.x)));
            th = (uint64_t)tl | ((uint64_t)th2 << 32); FMA2(sc[3], th, wp0);
            tl = __float_as_uint(tanh_fast(fv.y + u64lo(q0.y)));
            th2 = __float_as_uint(tanh_fast(fv.y + u64hi(q0.y)));
            th = (uint64_t)tl | ((uint64_t)th2 << 32); FMA2(sc[0], th, wp1);
            tl = __float_as_uint(tanh_fast(fv.y + u64lo(q1.y)));
            th2 = __float_as_uint(tanh_fast(fv.y + u64hi(q1.y)));
            th = (uint64_t)tl | ((uint64_t)th2 << 32); FMA2(sc[1], th, wp1);
            tl = __float_as_uint(tanh_fast(fv.y + u64lo(q2.y)));
            th2 = __float_as_uint(tanh_fast(fv.y + u64hi(q2.y)));
            th = (uint64_t)tl | ((uint64_t)th2 << 32); FMA2(sc[2], th, wp1);
            tl = __float_as_uint(tanh_fast(fv.y + u64lo(q3.y)));
            th2 = __float_as_uint(tanh_fast(fv.y + u64hi(q3.y)));
            th = (uint64_t)tl | ((uint64_t)th2 << 32); FMA2(sc[3], th, wp1);
        }
#pragma unroll
        for (int tp = 0; tp < 4; tp++) sc[tp] = wredsum2(sc[tp]);
        if (lane == 0) {
#pragma unroll
            for (int tp = 0; tp < 4; tp++) {
                float e0 = __expf(u64lo(sc[tp]));
                float e1 = __expf(u64hi(sc[tp]));
                attp[tp * 256 + pq] = make_float2(e0, e1);
                uint64_t ev = (uint64_t)__float_as_uint(e0) | ((uint64_t)__float_as_uint(e1) << 32);
                asm("add.rn.f32x2 %0, %0, %1;" : "+l"(ps[tp]) : "l"(ev));
            }
        }
    }
    if (lane == 0) {
#pragma unroll
        for (int tp = 0; tp < 4; tp++)
            red8p[w * 4 + tp] = make_float2(u64lo(ps[tp]), u64hi(ps[tp]));
    }
    __syncthreads();
    if (tid < 4) {
        float sx = 0.f, sy = 0.f;
#pragma unroll
        for (int ww = 0; ww < 8; ww++) {
            float2 v = red8p[ww * 4 + tid];
            sx += v.x; sy += v.y;
        }
        sinvp[tid] = make_float2(1.f / sx, 1.f / sy);
    }
    __syncthreads();
    for (int pq = tid; pq < 256; pq += 256) {
#pragma unroll
        for (int tp = 0; tp < 4; tp++) {
            float2 v = attp[tp * 256 + pq];
            float2 s = sinvp[tp];
            attp[tp * 256 + pq] = make_float2(v.x * s.x, v.y * s.y);
        }
    }
    __syncthreads();

#pragma unroll 1
    for (int c = w; c < 512; c += 8) {
        uint64_t gc[4] = {0ull, 0ull, 0ull, 0ull};
        const float2* fr = (const float2*)(feat + ((size_t)b * CF + c) * PP);
#pragma unroll
        for (int i = 0; i < 4; i++) {
            int p2 = lane + 32 * i;
            float2 fv = fr[p2];
            uint64_t fp0, fp1;
            PACK2(fp0, fv.x);
            PACK2(fp1, fv.y);
#pragma unroll
            for (int tp = 0; tp < 4; tp++) {
                ulonglong2 aq = *(const ulonglong2*)&attp[tp * 256 + 2 * p2];
                FMA2(gc[tp], aq.x, fp0);
                FMA2(gc[tp], aq.y, fp1);
            }
        }
#pragma unroll
        for (int tp = 0; tp < 4; tp++) gc[tp] = wredsum2(gc[tp]);
        if (lane == 0) {
#pragma unroll
            for (int tp = 0; tp < 4; tp++)
                glp[tp * 512 + c] = make_float2(u64lo(gc[tp]), u64hi(gc[tp]));
        }
    }
    __syncthreads();

#pragma unroll 1
    for (int v = w; v < VV1; v += 8) {
        uint64_t lg[4] = {0ull, 0ull, 0ull, 0ull};
        const float2* wr = (const float2*)(Wout + (size_t)v * 1024);
#pragma unroll
        for (int i = 0; i < 16; i++) {
            int k2 = lane + 32 * i;
            float2 wv = wr[k2];
            const float2* plane = (i < 8) ? h1p : glp;
            int kk = (i < 8) ? (2 * k2) : (2 * (k2 - 256));
            uint64_t wp0, wp1;
            PACK2(wp0, wv.x);
            PACK2(wp1, wv.y);
#pragma unroll
            for (int tp = 0; tp < 4; tp++) {
                ulonglong2 hq = *(const ulonglong2*)&plane[tp * 512 + kk];
                FMA2(lg[tp], hq.x, wp0);
                FMA2(lg[tp], hq.y, wp1);
            }
        }
#pragma unroll
        for (int tp = 0; tp < 4; tp++) lg[tp] = wredsum2(lg[tp]);
        if (lane == 0) {
            float bv = bout[v];
#pragma unroll
            for (int tp = 0; tp < 4; tp++) {
                int ja = 2 * tp, jb = 2 * tp + 1;
                if (ja < nt) out[((size_t)b * NSTEPS + t0 + ja) * VV1 + v] = u64lo(lg[tp]) + bv;
                if (jb < nt) out[((size_t)b * NSTEPS + t0 + jb) * VV1 + v] = u64hi(lg[tp]) + bv;
            }
        }
    }
}

// ---------------- launch ----------------
extern "C" void kernel_launch(void* const* d_in, const int* in_sizes, int n_in,
                              void* d_out, int out_size) {
    (void)in_sizes; (void)n_in; (void)out_size;
    const float* features = (const float*)d_in[0];
    const int*   gt       = (const int*)d_in[2];
    const float* W_feat   = (const float*)d_in[3];
    const float* b_feat   = (const float*)d_in[4];
    const float* W_state  = (const float*)d_in[5];
    const float* w_att    = (const float*)d_in[6];
    const float* W_embed  = (const float*)d_in[7];
    const float* wih0     = (const float*)d_in[8];
    const float* whh0     = (const float*)d_in[9];
    const float* bih0     = (const float*)d_in[10];
    const float* bhh0     = (const float*)d_in[11];
    const float* wih1     = (const float*)d_in[12];
    const float* whh1     = (const float*)d_in[13];
    const float* bih1     = (const float*)d_in[14];
    const float* bhh1     = (const float*)d_in[15];
    const float* W_out    = (const float*)d_in[16];
    const float* b_out    = (const float*)d_in[17];
    float* out = (float*)d_out;

    static const int DEC_SMEM = (24576 + 16512 + 2112 + 2112 + 32) * 4;
    static const int XG_SMEM = 2 * CSTAGE + 1024;
    cudaFuncSetAttribute(k_lstm, cudaFuncAttributeMaxDynamicSharedMemorySize, DEC_SMEM);
    cudaFuncSetAttribute(k_conv_mma, cudaFuncAttributeMaxDynamicSharedMemorySize, CONV_SMEM);
    cudaFuncSetAttribute(k_xgemm, cudaFuncAttributeMaxDynamicSharedMemorySize, XG_SMEM);
    cudaFuncSetAttribute(k_attn, cudaFuncAttributeMaxDynamicSharedMemorySize, ATT_SMEM);

    k_init<<<4096, 256>>>(gt, W_embed, wih0);
    k_prep_feat<<<dim3(8, 16, 32), dim3(32, 32)>>>(features);
    k_prep_w<<<512, 256>>>(W_feat);
    k_conv_mma<<<256, 256, CONV_SMEM>>>(b_feat);
    k_xgemm<<<128, 256, XG_SMEM>>>();
    k_lstm<<<NBLK, NTHR, DEC_SMEM>>>(whh0, bih0, bhh0,
                                     wih1, whh1, bih1, bhh1);
    k_attn<<<dim3(32, 4), 256, ATT_SMEM>>>(features, W_state, w_att, W_out, b_out, out);
}